// round 1
// baseline (speedup 1.0000x reference)
#include <cuda_runtime.h>
#include <math.h>

#define T_LEN 512
#define BATCH 64
#define ISZ   256
#define HID   512
#define GH    2048   // 4*HID, gate order f,i,o,c

// ---------------- device scratch (no allocations allowed) ----------------
__device__ float g_gx[(size_t)T_LEN * GH * BATCH];  // [t][n=g*512+h][b], 256 MB
__device__ float g_hT[HID * BATCH];                 // h state, [h][b]
__device__ float g_c [HID * BATCH];                 // c state, [h][b]

// ---------------- init: zero recurrent state every replay ----------------
__global__ void init_state_kernel() {
    int idx = blockIdx.x * blockDim.x + threadIdx.x;
    if (idx < HID * BATCH) { g_hT[idx] = 0.0f; g_c[idx] = 0.0f; }
}

// ---------------- gx = x @ Wx^T + bx  -> g_gx[t][n][b] ----------------
// grid (64 n-tiles, 512 t), block 256. CTA tile: 32 rows(n) x 64 batch, K=256.
__global__ __launch_bounds__(256) void gx_kernel(const float* __restrict__ x,
                                                 const float* __restrict__ Wx,
                                                 const float* __restrict__ bx) {
    extern __shared__ float sm[];
    float* x_s = sm;               // [256][65] padded transpose: x_s[i*65+b]
    float* Ws  = sm + 256 * 65;    // [32][256] rows n0..n0+31
    const int tid = threadIdx.x;
    const int t   = blockIdx.y;
    const int n0  = blockIdx.x * 32;

    // stage x[t] (b-major in gmem) -> transposed padded smem
    const float* xt = x + (size_t)t * BATCH * ISZ;
    #pragma unroll 4
    for (int r = 0; r < 64; r++) {
        int idx = r * 256 + tid;
        int b = idx >> 8;          // idx / 256
        int i = idx & 255;         // idx % 256
        x_s[i * 65 + b] = xt[idx];
    }
    // stage Wx rows n0..n0+31 (row-major, contiguous)
    const float* Wrow = Wx + (size_t)n0 * ISZ;
    #pragma unroll 4
    for (int r = 0; r < 32; r++) {
        int idx = r * 256 + tid;
        Ws[idx] = Wrow[idx];
    }
    __syncthreads();

    const int b  = tid & 63;
    const int ng = tid >> 6;       // 0..3, each thread owns 8 rows
    float acc[8];
    #pragma unroll
    for (int j = 0; j < 8; j++) acc[j] = 0.0f;

    const float4* Ws4 = (const float4*)(Ws + (ng * 8) * ISZ);  // 64 float4 per row
    #pragma unroll 2
    for (int k4 = 0; k4 < 64; k4++) {
        const int k = k4 * 4;
        const float xa = x_s[(k + 0) * 65 + b];
        const float xb = x_s[(k + 1) * 65 + b];
        const float xc = x_s[(k + 2) * 65 + b];
        const float xd = x_s[(k + 3) * 65 + b];
        #pragma unroll
        for (int j = 0; j < 8; j++) {
            float4 w = Ws4[j * 64 + k4];
            acc[j] += w.x * xa;
            acc[j] += w.y * xb;
            acc[j] += w.z * xc;
            acc[j] += w.w * xd;
        }
    }

    const size_t base = ((size_t)t * GH + n0 + ng * 8) * BATCH + b;
    #pragma unroll
    for (int j = 0; j < 8; j++) {
        g_gx[base + (size_t)j * BATCH] = acc[j] + __ldg(&bx[n0 + ng * 8 + j]);
    }
}

// ---------------- one recurrent step ----------------
// grid 128, block 256. CTA owns h in [h0, h0+4), all 4 gates, all 64 batch.
// Thread = one (h_local, b) cell: computes 4 gate dot products (K=512).
__global__ __launch_bounds__(256) void step_kernel(int t,
                                                   const float* __restrict__ Wh,
                                                   const float* __restrict__ bh,
                                                   float* __restrict__ h_seq,
                                                   float* __restrict__ out_hlast,
                                                   float* __restrict__ out_clast) {
    extern __shared__ float sm[];
    float* Ws = sm;                // [16][512], row r = g*4 + h_local
    float* hs = sm + 16 * HID;     // [k][b] = hs[k*64+b]
    const int tid = threadIdx.x;
    const int h0  = blockIdx.x * 4;

    // stage 16 Wh rows (g in 0..3, h_local in 0..3): rows g*512 + h0 + hl
    #pragma unroll 4
    for (int it = 0; it < 32; it++) {
        int idx = it * 256 + tid;          // 0..8191
        int r = idx >> 9;                  // smem row 0..15
        int k = idx & 511;
        int g  = r >> 2;
        int hl = r & 3;
        Ws[idx] = Wh[((size_t)(g * HID + h0 + hl)) * HID + k];
    }
    // stage h_prev: g_hT layout [h][b] == hs layout [k][b] -> straight float4 copy
    const float4* src = (const float4*)g_hT;
    float4* dst = (float4*)hs;
    #pragma unroll 4
    for (int it = 0; it < 32; it++) {
        int idx = it * 256 + tid;          // 0..8191 float4s
        dst[idx] = src[idx];
    }
    __syncthreads();

    const int b  = tid & 63;
    const int hl = tid >> 6;               // 0..3
    const int h  = h0 + hl;

    float a0 = 0.0f, a1 = 0.0f, a2 = 0.0f, a3 = 0.0f;
    const float4* W0 = (const float4*)(Ws + (0 * 4 + hl) * HID);
    const float4* W1 = (const float4*)(Ws + (1 * 4 + hl) * HID);
    const float4* W2 = (const float4*)(Ws + (2 * 4 + hl) * HID);
    const float4* W3 = (const float4*)(Ws + (3 * 4 + hl) * HID);
    const float* hb = hs + b;

    #pragma unroll 4
    for (int k4 = 0; k4 < 128; k4++) {
        const float hv0 = hb[(4 * k4 + 0) * 64];
        const float hv1 = hb[(4 * k4 + 1) * 64];
        const float hv2 = hb[(4 * k4 + 2) * 64];
        const float hv3 = hb[(4 * k4 + 3) * 64];
        float4 w;
        w = W0[k4]; a0 += w.x * hv0; a0 += w.y * hv1; a0 += w.z * hv2; a0 += w.w * hv3;
        w = W1[k4]; a1 += w.x * hv0; a1 += w.y * hv1; a1 += w.z * hv2; a1 += w.w * hv3;
        w = W2[k4]; a2 += w.x * hv0; a2 += w.y * hv1; a2 += w.z * hv2; a2 += w.w * hv3;
        w = W3[k4]; a3 += w.x * hv0; a3 += w.y * hv1; a3 += w.z * hv2; a3 += w.w * hv3;
    }

    // gate preactivations: a_g + gx[t][g*512+h][b] + bh[g*512+h]
    const size_t gxb = ((size_t)t * GH + h) * BATCH + b;     // g=0 slot
    const float pf = a0 + g_gx[gxb + (size_t)0 * HID * BATCH] + __ldg(&bh[0 * HID + h]);
    const float pi = a1 + g_gx[gxb + (size_t)1 * HID * BATCH] + __ldg(&bh[1 * HID + h]);
    const float po = a2 + g_gx[gxb + (size_t)2 * HID * BATCH] + __ldg(&bh[2 * HID + h]);
    const float pc = a3 + g_gx[gxb + (size_t)3 * HID * BATCH] + __ldg(&bh[3 * HID + h]);

    const float f  = 1.0f / (1.0f + expf(-pf));
    const float ig = 1.0f / (1.0f + expf(-pi));
    const float o  = 1.0f / (1.0f + expf(-po));
    const float cg = tanhf(pc);

    const int sidx = h * BATCH + b;
    const float c  = f * g_c[sidx] + ig * cg;
    const float hn = o * tanhf(c);

    g_c[sidx]  = c;
    g_hT[sidx] = hn;
    h_seq[((size_t)t * BATCH + b) * HID + h] = hn;
    if (t == T_LEN - 1) {
        out_hlast[(size_t)b * HID + h] = hn;
        out_clast[(size_t)b * HID + h] = c;
    }
}

// ---------------- launch ----------------
extern "C" void kernel_launch(void* const* d_in, const int* in_sizes, int n_in,
                              void* d_out, int out_size) {
    const float* x  = (const float*)d_in[0];
    const float* Wx = (const float*)d_in[1];
    const float* bx = (const float*)d_in[2];
    const float* Wh = (const float*)d_in[3];
    const float* bh = (const float*)d_in[4];

    float* out       = (float*)d_out;
    float* out_hlast = out + (size_t)T_LEN * BATCH * HID;
    float* out_clast = out_hlast + (size_t)BATCH * HID;

    const int gx_smem   = (256 * 65 + 32 * 256) * sizeof(float);   // 99328 B
    const int step_smem = (16 * HID + HID * BATCH) * sizeof(float); // 163840 B
    cudaFuncSetAttribute(gx_kernel,   cudaFuncAttributeMaxDynamicSharedMemorySize, gx_smem);
    cudaFuncSetAttribute(step_kernel, cudaFuncAttributeMaxDynamicSharedMemorySize, step_smem);

    init_state_kernel<<<64, 512>>>();
    gx_kernel<<<dim3(64, 512), 256, gx_smem>>>(x, Wx, bx);
    for (int t = 0; t < T_LEN; t++) {
        step_kernel<<<128, 256, step_smem>>>(t, Wh, bh, out, out_hlast, out_clast);
    }
}

// round 2
// speedup vs baseline: 1.0888x; 1.0888x over previous
#include <cuda_runtime.h>
#include <math.h>

#define T_LEN 512
#define BATCH 64
#define ISZ   256
#define HID   512
#define GH    2048   // 4*HID, gate order f,i,o,c
#define NCTA  128
#define NTHR  256

// ---------------- device scratch (no allocations allowed) ----------------
__device__ float g_gx[(size_t)T_LEN * GH * BATCH];  // [t][n=g*512+h][b]
__device__ float g_h[2][HID * BATCH];               // double-buffered h, [h][b]
__device__ unsigned g_bar;                          // grid barrier counter

// ---------------- packed f32x2 FMA (FFMA2, sm_100+) ----------------
union F2U { float2 f; unsigned long long u; };
__device__ __forceinline__ float2 ffma2(float2 a, float2 b, float2 c) {
    F2U A, B, C, D; A.f = a; B.f = b; C.f = c;
    asm("fma.rn.f32x2 %0, %1, %2, %3;" : "=l"(D.u) : "l"(A.u), "l"(B.u), "l"(C.u));
    return D.f;
}

// ---------------- init: zero h buffers + barrier each replay ----------------
__global__ void init_state_kernel() {
    int idx = blockIdx.x * blockDim.x + threadIdx.x;
    if (idx < 2 * HID * BATCH) ((float*)g_h)[idx] = 0.0f;
    if (idx == 0) g_bar = 0;
}

// ---------------- gx = x @ Wx^T + bx  -> g_gx[t][n][b] ----------------
__global__ __launch_bounds__(256) void gx_kernel(const float* __restrict__ x,
                                                 const float* __restrict__ Wx,
                                                 const float* __restrict__ bx) {
    extern __shared__ float sm[];
    float* x_s = sm;               // [256][65] padded transpose
    float* Ws  = sm + 256 * 65;    // [32][256]
    const int tid = threadIdx.x;
    const int t   = blockIdx.y;
    const int n0  = blockIdx.x * 32;

    const float* xt = x + (size_t)t * BATCH * ISZ;
    #pragma unroll 4
    for (int r = 0; r < 64; r++) {
        int idx = r * 256 + tid;
        int b = idx >> 8;
        int i = idx & 255;
        x_s[i * 65 + b] = xt[idx];
    }
    const float* Wrow = Wx + (size_t)n0 * ISZ;
    #pragma unroll 4
    for (int r = 0; r < 32; r++) {
        int idx = r * 256 + tid;
        Ws[idx] = Wrow[idx];
    }
    __syncthreads();

    const int b  = tid & 63;
    const int ng = tid >> 6;
    float acc[8];
    #pragma unroll
    for (int j = 0; j < 8; j++) acc[j] = 0.0f;

    const float4* Ws4 = (const float4*)(Ws + (ng * 8) * ISZ);
    #pragma unroll 2
    for (int k4 = 0; k4 < 64; k4++) {
        const int k = k4 * 4;
        const float xa = x_s[(k + 0) * 65 + b];
        const float xb = x_s[(k + 1) * 65 + b];
        const float xc = x_s[(k + 2) * 65 + b];
        const float xd = x_s[(k + 3) * 65 + b];
        #pragma unroll
        for (int j = 0; j < 8; j++) {
            float4 w = Ws4[j * 64 + k4];
            acc[j] += w.x * xa;
            acc[j] += w.y * xb;
            acc[j] += w.z * xc;
            acc[j] += w.w * xd;
        }
    }

    const size_t base = ((size_t)t * GH + n0 + ng * 8) * BATCH + b;
    #pragma unroll
    for (int j = 0; j < 8; j++) {
        g_gx[base + (size_t)j * BATCH] = acc[j] + __ldg(&bx[n0 + ng * 8 + j]);
    }
}

// ---------------- persistent recurrence kernel ----------------
// 128 CTAs (1/SM, all resident) x 256 threads. CTA owns h in [h0, h0+4).
// Thread = (ks, hl, bp): ks = K half, hl = h_local 0..3, bp = batch pair 0..31.
// Each thread: 4 gate partial dots over K=256 for batches (2bp, 2bp+1) via FFMA2.
// Wh stays in smem (duplicated pairs) for all 512 steps. c lives in registers.
__global__ __launch_bounds__(NTHR) void lstm_persistent(
        const float* __restrict__ Wh,
        const float* __restrict__ bh,
        float* __restrict__ h_seq,
        float* __restrict__ out_hlast,
        float* __restrict__ out_clast) {
    extern __shared__ float sm[];
    float2* Wd2 = (float2*)sm;                 // [16 rows][512 k] dup pairs: 65536 B
    float*  hs  = sm + 16384;                  // [k][b] h stage: 131072 B
    float2* red = (float2*)(sm + 16384 + 32768); // [128 threads][4 gates]: 4096 B

    const int tid = threadIdx.x;
    const int h0  = blockIdx.x * 4;
    const int bp  = tid & 31;
    const int hl  = (tid >> 5) & 3;
    const int ks  = tid >> 7;                  // 0 or 1
    const int h   = h0 + hl;

    // ---- stage Wh once, duplicated: Wd2[row*512+k] = (w, w), row = g*4+hl
    #pragma unroll 4
    for (int it = 0; it < 32; it++) {
        int idx = it * 256 + tid;              // 0..8191 = row*512 + k
        int r = idx >> 9, k = idx & 511;
        int g = r >> 2, hll = r & 3;
        float w = Wh[((size_t)(g * HID + h0 + hll)) * HID + k];
        Wd2[idx] = make_float2(w, w);
    }

    // per-thread constants (ks==0 threads do the epilogue)
    float bhf = 0.f, bhi = 0.f, bho = 0.f, bhc = 0.f;
    if (ks == 0) {
        bhf = __ldg(&bh[0 * HID + h]);
        bhi = __ldg(&bh[1 * HID + h]);
        bho = __ldg(&bh[2 * HID + h]);
        bhc = __ldg(&bh[3 * HID + h]);
    }
    float c0 = 0.0f, c1 = 0.0f;                // cell state for (h, 2bp) and (h, 2bp+1)

    const ulonglong2* W0 = (const ulonglong2*)(Wd2 + (0 * 4 + hl) * 512 + ks * 256);
    const ulonglong2* W1 = (const ulonglong2*)(Wd2 + (1 * 4 + hl) * 512 + ks * 256);
    const ulonglong2* W2 = (const ulonglong2*)(Wd2 + (2 * 4 + hl) * 512 + ks * 256);
    const ulonglong2* W3 = (const ulonglong2*)(Wd2 + (3 * 4 + hl) * 512 + ks * 256);

    int cur = 0;
    for (int t = 0; t < T_LEN; t++) {
        // prefetch gx for epilogue (independent of h, hide behind staging/compute)
        float2 gx0, gx1, gx2, gx3;
        if (ks == 0) {
            const size_t gbase = ((size_t)t * GH + h) * BATCH + 2 * bp;
            gx0 = __ldg((const float2*)(g_gx + gbase + (size_t)0 * HID * BATCH));
            gx1 = __ldg((const float2*)(g_gx + gbase + (size_t)1 * HID * BATCH));
            gx2 = __ldg((const float2*)(g_gx + gbase + (size_t)2 * HID * BATCH));
            gx3 = __ldg((const float2*)(g_gx + gbase + (size_t)3 * HID * BATCH));
        }

        // ---- stage h (global [h][b] -> smem [k][b], identical layout)
        {
            const float4* src = (const float4*)g_h[cur];
            float4* dst = (float4*)hs;
            #pragma unroll 8
            for (int it = 0; it < 32; it++) {
                int idx = it * 256 + tid;
                dst[idx] = src[idx];
            }
        }
        __syncthreads();

        // ---- compute: 4 gate dots over this thread's K half, batch pair packed
        float2 a0 = make_float2(0.f, 0.f), a1 = a0, a2 = a0, a3 = a0;
        const float2* hp = (const float2*)hs + ks * 256 * 32 + bp;  // element k at hp[k*32]

        #pragma unroll 4
        for (int kk = 0; kk < 64; kk++) {
            const float2 hv0 = hp[(4 * kk + 0) * 32];
            const float2 hv1 = hp[(4 * kk + 1) * 32];
            const float2 hv2 = hp[(4 * kk + 2) * 32];
            const float2 hv3 = hp[(4 * kk + 3) * 32];
            F2U wa, wb;
            ulonglong2 w;
            w = W0[2 * kk];     wa.u = w.x; wb.u = w.y;
            a0 = ffma2(hv0, wa.f, a0); a0 = ffma2(hv1, wb.f, a0);
            w = W0[2 * kk + 1]; wa.u = w.x; wb.u = w.y;
            a0 = ffma2(hv2, wa.f, a0); a0 = ffma2(hv3, wb.f, a0);
            w = W1[2 * kk];     wa.u = w.x; wb.u = w.y;
            a1 = ffma2(hv0, wa.f, a1); a1 = ffma2(hv1, wb.f, a1);
            w = W1[2 * kk + 1]; wa.u = w.x; wb.u = w.y;
            a1 = ffma2(hv2, wa.f, a1); a1 = ffma2(hv3, wb.f, a1);
            w = W2[2 * kk];     wa.u = w.x; wb.u = w.y;
            a2 = ffma2(hv0, wa.f, a2); a2 = ffma2(hv1, wb.f, a2);
            w = W2[2 * kk + 1]; wa.u = w.x; wb.u = w.y;
            a2 = ffma2(hv2, wa.f, a2); a2 = ffma2(hv3, wb.f, a2);
            w = W3[2 * kk];     wa.u = w.x; wb.u = w.y;
            a3 = ffma2(hv0, wa.f, a3); a3 = ffma2(hv1, wb.f, a3);
            w = W3[2 * kk + 1]; wa.u = w.x; wb.u = w.y;
            a3 = ffma2(hv2, wa.f, a3); a3 = ffma2(hv3, wb.f, a3);
        }

        // ---- reduce K halves
        if (ks == 1) {
            red[(tid - 128) * 4 + 0] = a0;
            red[(tid - 128) * 4 + 1] = a1;
            red[(tid - 128) * 4 + 2] = a2;
            red[(tid - 128) * 4 + 3] = a3;
        }
        __syncthreads();

        if (ks == 0) {
            const float2 r0 = red[tid * 4 + 0];
            const float2 r1 = red[tid * 4 + 1];
            const float2 r2 = red[tid * 4 + 2];
            const float2 r3 = red[tid * 4 + 3];
            const float pf0 = a0.x + r0.x + gx0.x + bhf, pf1 = a0.y + r0.y + gx0.y + bhf;
            const float pi0 = a1.x + r1.x + gx1.x + bhi, pi1 = a1.y + r1.y + gx1.y + bhi;
            const float po0 = a2.x + r2.x + gx2.x + bho, po1 = a2.y + r2.y + gx2.y + bho;
            const float pc0 = a3.x + r3.x + gx3.x + bhc, pc1 = a3.y + r3.y + gx3.y + bhc;

            const float f0 = 1.0f / (1.0f + expf(-pf0));
            const float f1 = 1.0f / (1.0f + expf(-pf1));
            const float i0 = 1.0f / (1.0f + expf(-pi0));
            const float i1 = 1.0f / (1.0f + expf(-pi1));
            const float o0 = 1.0f / (1.0f + expf(-po0));
            const float o1 = 1.0f / (1.0f + expf(-po1));
            const float q0 = tanhf(pc0);
            const float q1 = tanhf(pc1);

            c0 = f0 * c0 + i0 * q0;
            c1 = f1 * c1 + i1 * q1;
            const float hn0 = o0 * tanhf(c0);
            const float hn1 = o1 * tanhf(c1);

            // next-step h buffer ([h][b], adjacent pair -> 8B store)
            *(float2*)&g_h[cur ^ 1][h * BATCH + 2 * bp] = make_float2(hn0, hn1);
            // h_seq output: [T][B][H]
            h_seq[((size_t)t * BATCH + 2 * bp) * HID + h]     = hn0;
            h_seq[((size_t)t * BATCH + 2 * bp + 1) * HID + h] = hn1;
            if (t == T_LEN - 1) {
                out_hlast[(size_t)(2 * bp) * HID + h]     = hn0;
                out_hlast[(size_t)(2 * bp + 1) * HID + h] = hn1;
                out_clast[(size_t)(2 * bp) * HID + h]     = c0;
                out_clast[(size_t)(2 * bp + 1) * HID + h] = c1;
            }
        }

        // ---- grid barrier (all 128 CTAs resident; spin is safe)
        __syncthreads();   // all writes in this CTA done
        if (tid == 0) {
            __threadfence();
            atomicAdd(&g_bar, 1u);
            const unsigned target = (unsigned)(t + 1) * NCTA;
            while (*(volatile unsigned*)&g_bar < target) { }
            __threadfence();
        }
        __syncthreads();
        cur ^= 1;
    }
}

// ---------------- launch ----------------
extern "C" void kernel_launch(void* const* d_in, const int* in_sizes, int n_in,
                              void* d_out, int out_size) {
    const float* x  = (const float*)d_in[0];
    const float* Wx = (const float*)d_in[1];
    const float* bx = (const float*)d_in[2];
    const float* Wh = (const float*)d_in[3];
    const float* bh = (const float*)d_in[4];

    float* out       = (float*)d_out;
    float* out_hlast = out + (size_t)T_LEN * BATCH * HID;
    float* out_clast = out_hlast + (size_t)BATCH * HID;

    const int gx_smem = (256 * 65 + 32 * 256) * sizeof(float);          // 99328 B
    const int ps_smem = (16384 + 32768 + 1024) * sizeof(float);        // 200704 B
    cudaFuncSetAttribute(gx_kernel,       cudaFuncAttributeMaxDynamicSharedMemorySize, gx_smem);
    cudaFuncSetAttribute(lstm_persistent, cudaFuncAttributeMaxDynamicSharedMemorySize, ps_smem);

    init_state_kernel<<<128, 512>>>();
    gx_kernel<<<dim3(64, 512), 256, gx_smem>>>(x, Wx, bx);
    lstm_persistent<<<NCTA, NTHR, ps_smem>>>(Wh, bh, out, out_hlast, out_clast);
}